// round 1
// baseline (speedup 1.0000x reference)
#include <cuda_runtime.h>
#include <cuda_bf16.h>
#include <cstdint>

#define N_USER 100000
#define N_ITEM 50000
#define N_NODES 150000
#define N_EDGES 1200000
#define D 64
#define OUTD 256
#define NEG_SLOPE 0.01f
#define EPS_NORM 1e-12f

// Scratch (device globals allowed; no dynamic allocation)
__device__ float g_E[N_NODES * D];      // current layer embedding (unnormalized)
__device__ float g_front[N_NODES * D];  // (H+I) @ E accumulator

// ---------------------------------------------------------------------------
// helpers
// ---------------------------------------------------------------------------
__device__ __forceinline__ float lrelu(float v) {
    return v >= 0.f ? v : NEG_SLOPE * v;
}

__device__ __forceinline__ unsigned long long pk2(float lo, float hi) {
    unsigned long long r;
    asm("mov.b64 %0, {%1, %2};" : "=l"(r) : "f"(lo), "f"(hi));
    return r;
}
__device__ __forceinline__ void unpk2(float& lo, float& hi, unsigned long long v) {
    asm("mov.b64 {%0, %1}, %2;" : "=f"(lo), "=f"(hi) : "l"(v));
}
__device__ __forceinline__ void fma2(unsigned long long& d, unsigned long long a,
                                     unsigned long long b) {
    asm("fma.rn.f32x2 %0, %1, %2, %0;" : "+l"(d) : "l"(a), "l"(b));
}

__device__ __forceinline__ void red_add_v4(float* p, float a, float b, float c, float d) {
    asm volatile("red.global.add.v4.f32 [%0], {%1, %2, %3, %4};"
                 :: "l"(p), "f"(a), "f"(b), "f"(c), "f"(d)
                 : "memory");
}

// ---------------------------------------------------------------------------
// kernel 0: build E0 = concat(user, item); write raw E0 into out[:, 0:64]
// ---------------------------------------------------------------------------
__global__ void k_init(const float* __restrict__ user, const float* __restrict__ item,
                       float* __restrict__ out) {
    int idx = blockIdx.x * blockDim.x + threadIdx.x;  // one float4 per thread
    if (idx >= N_NODES * (D / 4)) return;
    int row = idx >> 4;
    int c4 = (idx & 15) << 2;
    float4 v;
    if (row < N_USER)
        v = *reinterpret_cast<const float4*>(&user[row * D + c4]);
    else
        v = *reinterpret_cast<const float4*>(&item[(row - N_USER) * D + c4]);
    *reinterpret_cast<float4*>(&g_E[row * D + c4]) = v;
    *reinterpret_cast<float4*>(&out[row * OUTD + c4]) = v;
}

// ---------------------------------------------------------------------------
// kernel 1: front = E (the +I term)
// ---------------------------------------------------------------------------
__global__ void k_copy() {
    int idx = blockIdx.x * blockDim.x + threadIdx.x;
    if (idx >= N_NODES * (D / 4)) return;
    reinterpret_cast<float4*>(g_front)[idx] = reinterpret_cast<const float4*>(g_E)[idx];
}

// ---------------------------------------------------------------------------
// kernel 2: SpMM scatter: front[row] += val * E[col], 16 threads per edge
// ---------------------------------------------------------------------------
__global__ void k_spmm(const int* __restrict__ erow, const int* __restrict__ ecol,
                       const float* __restrict__ eval_) {
    int tid = blockIdx.x * blockDim.x + threadIdx.x;
    int e = tid >> 4;
    if (e >= N_EDGES) return;
    int c4 = (tid & 15) << 2;
    int r = __ldg(&erow[e]);
    int c = __ldg(&ecol[e]);
    float v = __ldg(&eval_[e]);
    float4 x = *reinterpret_cast<const float4*>(&g_E[c * D + c4]);
    red_add_v4(&g_front[r * D + c4], v * x.x, v * x.y, v * x.z, v * x.w);
}

// ---------------------------------------------------------------------------
// kernel 3: dense layer.
//   out_row = lrelu(front @ Wf^T + bf) + lrelu((E*front) @ Wb^T + bb)
//   E <- out_row (in place, row-local); out[:, 64*(l+1):64*(l+2)] = out_row / ||out_row||
// blockDim (32,4). Each warp processes 8 rows as 4 f32x2-packed row pairs.
// ---------------------------------------------------------------------------
#define GROUPS (N_NODES / 8)          // 18750
#define DENSE_BLOCKS ((GROUPS + 3) / 4)

__global__ __launch_bounds__(128) void k_dense(const float* __restrict__ Wf,
                                               const float* __restrict__ bf,
                                               const float* __restrict__ Wb,
                                               const float* __restrict__ bb,
                                               float* __restrict__ out, int layer) {
    __shared__ float Wtf[D * D];   // Wtf[k*64+j] = Wf[j*64+k]
    __shared__ float Wtb[D * D];
    __shared__ float2 x2s[4][4][D];  // [warp][pair][k] -> {front[2p][k], front[2p+1][k]}
    __shared__ float2 y2s[4][4][D];  // same for E*front

    int tid = threadIdx.y * 32 + threadIdx.x;
    int lane = threadIdx.x;
    int ty = threadIdx.y;

    // load W transposed (coalesced gmem read)
    for (int t = tid; t < D * D; t += 128) {
        int j = t >> 6, k = t & 63;
        Wtf[k * D + j] = Wf[t];
        Wtb[k * D + j] = Wb[t];
    }
    __syncthreads();

    int group = blockIdx.x * 4 + ty;
    if (group >= GROUPS) return;
    int rb = group * 8;

    // stage 8 rows (4 pairs) of front and E*front, float2-interleaved by row pair
    #pragma unroll
    for (int p = 0; p < 4; p++) {
        int r0 = (rb + 2 * p) * D;
        int r1 = r0 + D;
        #pragma unroll
        for (int h = 0; h < 2; h++) {
            int k = lane + h * 32;
            float a0 = g_front[r0 + k];
            float a1 = g_front[r1 + k];
            float e0 = g_E[r0 + k];
            float e1 = g_E[r1 + k];
            x2s[ty][p][k] = make_float2(a0, a1);
            y2s[ty][p][k] = make_float2(a0 * e0, a1 * e1);
        }
    }
    __syncwarp();

    float bfv0 = bf[lane], bfv1 = bf[lane + 32];
    float bbv0 = bb[lane], bbv1 = bb[lane + 32];

    unsigned long long sf0[4], sf1[4], sb0[4], sb1[4];
    #pragma unroll
    for (int p = 0; p < 4; p++) {
        sf0[p] = pk2(bfv0, bfv0);
        sf1[p] = pk2(bfv1, bfv1);
        sb0[p] = pk2(bbv0, bbv0);
        sb1[p] = pk2(bbv1, bbv1);
    }

    #pragma unroll 4
    for (int k = 0; k < D; k++) {
        float wf0 = Wtf[k * D + lane];
        float wf1 = Wtf[k * D + 32 + lane];
        float wb0 = Wtb[k * D + lane];
        float wb1 = Wtb[k * D + 32 + lane];
        unsigned long long wf0p = pk2(wf0, wf0);
        unsigned long long wf1p = pk2(wf1, wf1);
        unsigned long long wb0p = pk2(wb0, wb0);
        unsigned long long wb1p = pk2(wb1, wb1);
        #pragma unroll
        for (int p = 0; p < 4; p++) {
            unsigned long long xv =
                *reinterpret_cast<const unsigned long long*>(&x2s[ty][p][k]);
            unsigned long long yv =
                *reinterpret_cast<const unsigned long long*>(&y2s[ty][p][k]);
            fma2(sf0[p], xv, wf0p);
            fma2(sf1[p], xv, wf1p);
            fma2(sb0[p], yv, wb0p);
            fma2(sb1[p], yv, wb1p);
        }
    }

    int ocol = (layer + 1) * D;
    #pragma unroll
    for (int p = 0; p < 4; p++) {
        float f0lo, f0hi, f1lo, f1hi, b0lo, b0hi, b1lo, b1hi;
        unpk2(f0lo, f0hi, sf0[p]);
        unpk2(f1lo, f1hi, sf1[p]);
        unpk2(b0lo, b0hi, sb0[p]);
        unpk2(b1lo, b1hi, sb1[p]);

        int row0 = rb + 2 * p;
        int row1 = row0 + 1;

        float o00 = lrelu(f0lo) + lrelu(b0lo);  // row0, j=lane
        float o01 = lrelu(f1lo) + lrelu(b1lo);  // row0, j=lane+32
        float o10 = lrelu(f0hi) + lrelu(b0hi);  // row1, j=lane
        float o11 = lrelu(f1hi) + lrelu(b1hi);  // row1, j=lane+32

        float ss0 = o00 * o00 + o01 * o01;
        float ss1 = o10 * o10 + o11 * o11;
        #pragma unroll
        for (int d = 16; d > 0; d >>= 1) {
            ss0 += __shfl_xor_sync(0xffffffffu, ss0, d);
            ss1 += __shfl_xor_sync(0xffffffffu, ss1, d);
        }
        float inv0 = 1.f / fmaxf(sqrtf(ss0), EPS_NORM);
        float inv1 = 1.f / fmaxf(sqrtf(ss1), EPS_NORM);

        g_E[row0 * D + lane] = o00;
        g_E[row0 * D + 32 + lane] = o01;
        g_E[row1 * D + lane] = o10;
        g_E[row1 * D + 32 + lane] = o11;

        out[row0 * OUTD + ocol + lane] = o00 * inv0;
        out[row0 * OUTD + ocol + 32 + lane] = o01 * inv0;
        out[row1 * OUTD + ocol + lane] = o10 * inv1;
        out[row1 * OUTD + ocol + 32 + lane] = o11 * inv1;
    }
}

// ---------------------------------------------------------------------------
extern "C" void kernel_launch(void* const* d_in, const int* in_sizes, int n_in,
                              void* d_out, int out_size) {
    const float* user = (const float*)d_in[0];
    const float* item = (const float*)d_in[1];
    const int* erow = (const int*)d_in[2];
    const int* ecol = (const int*)d_in[3];
    const float* eval_ = (const float*)d_in[4];
    const float* Wf = (const float*)d_in[5];
    const float* bf = (const float*)d_in[6];
    const float* Wb = (const float*)d_in[7];
    const float* bb = (const float*)d_in[8];
    float* out = (float*)d_out;

    const int vec_elems = N_NODES * (D / 4);               // 2.4M float4 units
    const int vec_blocks = (vec_elems + 255) / 256;
    const int spmm_blocks = (N_EDGES * 16 + 255) / 256;    // 75000

    k_init<<<vec_blocks, 256>>>(user, item, out);
    for (int l = 0; l < 3; l++) {
        k_copy<<<vec_blocks, 256>>>();
        k_spmm<<<spmm_blocks, 256>>>(erow, ecol, eval_);
        k_dense<<<DENSE_BLOCKS, dim3(32, 4)>>>(Wf + l * D * D, bf + l * D,
                                               Wb + l * D * D, bb + l * D, out, l);
    }
}